// round 14
// baseline (speedup 1.0000x reference)
#include <cuda_runtime.h>

// Izhikevich 6-neuron network, T sequential steps. R12 math (bit-exact orbit A)
// + single-STS publish on warp0: spikes packed as float X = z2 + 2*z3 + 4*z4.
// warp0: LLBN->EBN->IFN. warp1: TN->MN + every-boundary detection. warp2: store.
// Grid-parallel periodic tail copy in a second kernel.
// Output: [spikes[5][T] | volts[5][T]]

#define BATCH 16
#define RS_MASK 255
#define RING_BATCHES 4
#define AUX_MASK 15
#define NSLOT 28

__device__ int g_det[3];     // [0]=flag, [1]=tcut (step), [2]=t0 (step)

__device__ __forceinline__ float fset_ge30(float a) {
    float r;
    asm("set.ge.f32.f32 %0, %1, %2;" : "=f"(r) : "f"(a), "f"(30.0f));
    return r;
}
__device__ __forceinline__ void st_rel(int* p, int v) {
    asm volatile("st.release.cta.u32 [%0], %1;" :: "l"(p), "r"(v) : "memory");
}
__device__ __forceinline__ int ld_acq(int* p) {
    int v;
    asm volatile("ld.acquire.cta.u32 %0, [%1];" : "=r"(v) : "l"(p) : "memory");
    return v;
}
__device__ __forceinline__ int fb(float x) { return __float_as_int(x); }
__device__ __forceinline__ float ib(int x) { return __int_as_float(x); }
// decode spike bit from packed float X in {0..7}: returns 1.0f or 0.0f
__device__ __forceinline__ float zdec(float X, int bit) {
    int xi = __float2int_rn(X);
    return ib((0 - ((xi >> bit) & 1)) & 0x3F800000);
}

__global__ void __launch_bounds__(128, 1)
izh_sim(const float* __restrict__ in_mat, int n_mat,
        const float* __restrict__ w12, float* __restrict__ out, int T) {
    __shared__ __align__(16) float ring0[256 * 4];   // v2,v3,v4,X (X = z2+2z3+4z4)
    __shared__ __align__(16) float ring1[256 * 4];   // z5,v5,z6,v6
    __shared__ float auxst[16 * 8];                  // warp0 state @ batch starts
    __shared__ unsigned shash[NSLOT];
    __shared__ int     sbat[NSLOT];
    __shared__ float   ssnap[NSLOT][13];
    __shared__ float red[4];
    __shared__ int fl[4];   // [0] w0 batches, [1] w1 batches, [2] consumer, [3] det

    const int tid = threadIdx.x;
    if (tid == 0) { fl[0] = 0; fl[1] = 0; fl[2] = 0; fl[3] = 0; }
    if (tid < NSLOT) { shash[tid] = 0u; sbat[tid] = -1; }

    // ---- reduction: sum(input_mat) ----
    float s = 0.0f;
    for (int i = tid; i < n_mat; i += 128) s += in_mat[i];
    #pragma unroll
    for (int o = 16; o; o >>= 1) s += __shfl_xor_sync(0xffffffffu, s, o);
    if ((tid & 31) == 0) red[tid >> 5] = s;
    __syncthreads();

    const int nbat = (T + BATCH - 1) / BATCH;

    // ================= warp0 lane0: LLBN -> EBN -> IFN =================
    if (tid == 0) {
        const float total = red[0] + red[1] + red[2] + red[3];
        const float z_plus = total * w12[0];
        const float C2 = 35.0f + 0.25f * w12[2] * (z_plus * w12[1]);
        const float B2 = 0.25f * w12[3];
        const float A2 = -0.25f * w12[2] * w12[7];
        const float C3 = 35.0f + 0.25f * (z_plus * w12[4]);
        const float A3 = 0.25f * w12[5];
        const float A4 = 0.25f * w12[6];

        float v2 = -60.0f, u2 = 4.5f;
        float v3 = -64.0f, u3 = -16.0f;
        float v4 = -64.0f, u4 = -16.0f;
        float z2p = 0.0f, z4p = 0.0f;

        int si = 0;
        for (int b = 0; b < nbat; ++b) {
            if (ld_acq(&fl[3])) break;
            bool stop = false;
            while (b - ld_acq(&fl[2]) >= RING_BATCHES) {
                if (ld_acq(&fl[3])) { stop = true; break; }
            }
            if (stop) break;
            {   // publish state at this batch start (released by fl[0]=b+1)
                float* a = &auxst[(b & AUX_MASK) * 8];
                a[0] = v2; a[1] = u2; a[2] = v3; a[3] = u3;
                a[4] = v4; a[5] = u4; a[6] = z2p; a[7] = z4p;
            }
            const int n = min(BATCH, T - b * BATCH);
            #pragma unroll 4
            for (int i = 0; i < n; ++i, ++si) {
                // LLBN (a=.1,b=-.075,c=-55,d=6)
                float vv2 = v2 * v2;
                float b2  = fmaf(vv2, 0.01f, fmaf(v2, 2.25f, fmaf(u2, -0.25f, C2)));
                float v12 = fmaf(z4p, A2, fmaf(z2p, B2, b2));
                float z2  = fset_ge30(v12);
                float nu2 = fmaf(u2, 0.975f, v2 * -0.001875f);
                v2 = fmaf(z2, -55.0f - v12, v12);
                u2 = fmaf(z2, 6.0f, nu2);
                // EBN (a=.02,b=.25,c=-55,d=.05)
                float vv3 = v3 * v3;
                float b3  = fmaf(vv3, 0.01f, fmaf(v3, 2.25f, fmaf(u3, -0.25f, C3)));
                float v13 = fmaf(z2, A3, b3);
                float z3  = fset_ge30(v13);
                float nu3 = fmaf(u3, 0.995f, v3 * 0.00125f);
                v3 = fmaf(z3, -55.0f - v13, v13);
                u3 = fmaf(z3, 0.05f, nu3);
                // IFN (a=.02,b=.25,c=-65,d=6)
                float vv4 = v4 * v4;
                float b4  = fmaf(vv4, 0.01f, fmaf(v4, 2.25f, fmaf(u4, -0.25f, 35.0f)));
                float v14 = fmaf(z3, A4, b4);
                float z4  = fset_ge30(v14);
                float nu4 = fmaf(u4, 0.995f, v4 * 0.00125f);
                v4 = fmaf(z4, -65.0f - v14, v14);
                u4 = fmaf(z4, 6.0f, nu4);

                z2p = z2; z4p = z4;
                // pack spikes into one float (exact: X in {0..7})
                float X = fmaf(z4, 4.0f, fmaf(z3, 2.0f, z2));
                *(float4*)&ring0[(si & RS_MASK) * 4] = make_float4(v2, v3, v4, X);
            }
            st_rel(&fl[0], b + 1);
        }
    }

    // ================= warp1 lane0: TN -> MN + every-boundary detection ========
    if (tid == 32) {
        const float A5 = 0.25f * w12[9] * w12[8];
        const float B5 = 0.25f * w12[10];
        const float A6 = 0.25f * w12[11];
        float v5 = -70.0f, u5 = -14.0f;
        float v6 = -64.0f, u6 = -16.0f;
        float z5p = 0.0f;
        bool fired = false;
        int t0b = 0, tcb = 0;

        int si = 0;
        for (int b = 0; b < nbat; ++b) {
            while (ld_acq(&fl[0]) <= b) { }
            if (b >= 1) {
                const float* a = &auxst[(b & AUX_MASK) * 8];
                unsigned h = 0x811C9DC5u;
                h = h * 0x01000193u + (unsigned)fb(a[0]);
                h = h * 0x01000193u + (unsigned)fb(a[1]);
                h = h * 0x01000193u + (unsigned)fb(a[2]);
                h = h * 0x01000193u + (unsigned)fb(a[3]);
                h = h * 0x01000193u + (unsigned)fb(a[4]);
                h = h * 0x01000193u + (unsigned)fb(a[5]);
                h = h * 0x01000193u + (unsigned)fb(a[6]);
                h = h * 0x01000193u + (unsigned)fb(a[7]);
                h = h * 0x01000193u + (unsigned)fb(v5);
                h = h * 0x01000193u + (unsigned)fb(u5);
                h = h * 0x01000193u + (unsigned)fb(v6);
                h = h * 0x01000193u + (unsigned)fb(u6);
                h = h * 0x01000193u + (unsigned)fb(z5p);
                int hit = -1;
                #pragma unroll
                for (int k = 0; k < NSLOT; ++k)
                    if (shash[k] == h && sbat[k] >= 0) hit = k;
                if (hit >= 0) {
                    bool eq = (fb(a[0]) == fb(ssnap[hit][0])) &
                              (fb(a[1]) == fb(ssnap[hit][1])) &
                              (fb(a[2]) == fb(ssnap[hit][2])) &
                              (fb(a[3]) == fb(ssnap[hit][3])) &
                              (fb(a[4]) == fb(ssnap[hit][4])) &
                              (fb(a[5]) == fb(ssnap[hit][5])) &
                              (fb(a[6]) == fb(ssnap[hit][6])) &
                              (fb(a[7]) == fb(ssnap[hit][7])) &
                              (fb(v5)   == fb(ssnap[hit][8])) &
                              (fb(u5)   == fb(ssnap[hit][9])) &
                              (fb(v6)   == fb(ssnap[hit][10])) &
                              (fb(u6)   == fb(ssnap[hit][11])) &
                              (fb(z5p)  == fb(ssnap[hit][12]));
                    if (eq && sbat[hit] < b) {
                        fired = true; t0b = sbat[hit]; tcb = b;
                        st_rel(&fl[3], 1);
                        break;
                    }
                }
                {   // arm this boundary
                    int sl = b % NSLOT;
                    shash[sl] = h; sbat[sl] = b;
                    ssnap[sl][0] = a[0]; ssnap[sl][1] = a[1];
                    ssnap[sl][2] = a[2]; ssnap[sl][3] = a[3];
                    ssnap[sl][4] = a[4]; ssnap[sl][5] = a[5];
                    ssnap[sl][6] = a[6]; ssnap[sl][7] = a[7];
                    ssnap[sl][8] = v5;  ssnap[sl][9] = u5;
                    ssnap[sl][10] = v6; ssnap[sl][11] = u6;
                    ssnap[sl][12] = z5p;
                }
            }
            const int n = min(BATCH, T - b * BATCH);
            #pragma unroll 4
            for (int i = 0; i < n; ++i, ++si) {
                float X  = ring0[(si & RS_MASK) * 4 + 3];
                float z3 = zdec(X, 1);
                // TN (a=.02,b=.2,c=-65,d=6)
                float vv5 = v5 * v5;
                float b5  = fmaf(vv5, 0.01f, fmaf(v5, 2.25f, fmaf(u5, -0.25f, 35.0f)));
                float v15 = fmaf(z5p, B5, fmaf(z3, A5, b5));
                float z5  = fset_ge30(v15);
                float nu5 = fmaf(u5, 0.995f, v5 * 0.001f);
                v5 = fmaf(z5, -65.0f - v15, v15);
                u5 = fmaf(z5, 6.0f, nu5);
                // MN (a=.02,b=.25,c=-65,d=6)
                float vv6 = v6 * v6;
                float b6  = fmaf(vv6, 0.01f, fmaf(v6, 2.25f, fmaf(u6, -0.25f, 35.0f)));
                float v16 = fmaf(z5, A6, b6);
                float z6  = fset_ge30(v16);
                float nu6 = fmaf(u6, 0.995f, v6 * 0.00125f);
                v6 = fmaf(z6, -65.0f - v16, v16);
                u6 = fmaf(z6, 6.0f, nu6);

                z5p = z5;
                ((float4*)&ring1[(si & RS_MASK) * 4])[0] = make_float4(z5, v5, z6, v6);
            }
            st_rel(&fl[1], b + 1);
        }
        g_det[0] = fired ? 1 : 0;
        g_det[1] = tcb * BATCH;
        g_det[2] = t0b * BATCH;
    }

    // ================= warp2: store warp =================
    if (tid >= 64 && tid < 96) {
        const int lane = tid - 64;
        // rows: z2 z3 z4 z5 z6 v2 v3 v4 v5 v6
        // buf:   0  0  0  1  1  0  0  0  1  1   (mask 0x318)
        // col:   3  3  3  0  2  0  1  2  1  3   (rows 0-2 decode bit 'row' from X)
        for (int b = 0; b < nbat; ++b) {
            bool stop = false;
            for (;;) {
                if (ld_acq(&fl[1]) > b) break;
                if (ld_acq(&fl[3]) && ld_acq(&fl[1]) <= b) { stop = true; break; }
            }
            if (stop) break;
            const int base = b * BATCH;
            const int n = min(BATCH, T - base);
            if ((T & 3) == 0) {
                const int quads = n >> 2;
                const int units = 10 * quads;
                for (int u = lane; u < units; u += 32) {
                    const int row = u / quads;
                    const int q   = u - row * quads;
                    const int st  = base + q * 4;
                    const int buf = (0x318 >> row) & 1;
                    const int col = (row < 8) ? ((0x21020333u >> (4 * row)) & 15)
                                              : ((0x31u >> (4 * (row - 8))) & 15);
                    float x0, x1, x2, x3;
                    if (buf == 0) {
                        x0 = ring0[((st + 0) & RS_MASK) * 4 + col];
                        x1 = ring0[((st + 1) & RS_MASK) * 4 + col];
                        x2 = ring0[((st + 2) & RS_MASK) * 4 + col];
                        x3 = ring0[((st + 3) & RS_MASK) * 4 + col];
                    } else {
                        x0 = ring1[((st + 0) & RS_MASK) * 4 + col];
                        x1 = ring1[((st + 1) & RS_MASK) * 4 + col];
                        x2 = ring1[((st + 2) & RS_MASK) * 4 + col];
                        x3 = ring1[((st + 3) & RS_MASK) * 4 + col];
                    }
                    if (row < 3) {
                        x0 = zdec(x0, row); x1 = zdec(x1, row);
                        x2 = zdec(x2, row); x3 = zdec(x3, row);
                    }
                    *(float4*)&out[row * T + st] = make_float4(x0, x1, x2, x3);
                }
            } else {
                const int units = 10 * n;
                for (int u = lane; u < units; u += 32) {
                    const int row = u / n;
                    const int i   = u - row * n;
                    const int st  = base + i;
                    const int buf = (0x318 >> row) & 1;
                    const int col = (row < 8) ? ((0x21020333u >> (4 * row)) & 15)
                                              : ((0x31u >> (4 * (row - 8))) & 15);
                    float x = buf ? ring1[(st & RS_MASK) * 4 + col]
                                  : ring0[(st & RS_MASK) * 4 + col];
                    if (row < 3) x = zdec(x, row);
                    out[row * T + st] = x;
                }
            }
            __syncwarp();
            if (lane == 0) st_rel(&fl[2], b + 1);
        }
    }
}

// Grid-parallel periodic tail fill: out[r][t] = out[r][t0 + (t-t0) mod P], t >= tcut.
__global__ void izh_tail_copy(float* __restrict__ out, int T) {
    if (!g_det[0]) return;
    const int tcut = g_det[1];
    const int t0   = g_det[2];
    const int P    = tcut - t0;
    const int tail = T - tcut;
    if (tail <= 0 || P <= 0) return;
    const int total = 10 * tail;
    for (int idx = blockIdx.x * blockDim.x + threadIdx.x; idx < total;
         idx += gridDim.x * blockDim.x) {
        const int row = idx / tail;
        const int t   = tcut + (idx - row * tail);
        const int src = t0 + (t - t0) % P;
        out[row * T + t] = out[row * T + src];
    }
}

extern "C" void kernel_launch(void* const* d_in, const int* in_sizes, int n_in,
                              void* d_out, int out_size) {
    const float* in_mat = (const float*)d_in[0];
    const float* w12    = (const float*)d_in[1];
    int n_mat = in_sizes[0];
    int T = out_size / 10;
    izh_sim<<<1, 128>>>(in_mat, n_mat, w12, (float*)d_out, T);
    izh_tail_copy<<<256, 256>>>((float*)d_out, T);
}

// round 15
// speedup vs baseline: 1.2637x; 1.2637x over previous
#include <cuda_runtime.h>

// Izhikevich 6-neuron network, T sequential steps. R12 math (bit-exact orbit A)
// + every-boundary exact cycle detection + grid tail copy.
// ring0 repacked [z2,z3,z4,v4 | v2,v3]: warp0 publish = STS.128 + STS.64.
// warp0: LLBN->EBN->IFN. warp1: TN->MN + detection. warp2: store.
// Output: [spikes[5][T] | volts[5][T]]

#define BATCH 16
#define RS_MASK 255
#define RING_BATCHES 4
#define AUX_MASK 15
#define NSLOT 28

__device__ int g_det[3];     // [0]=flag, [1]=tcut (step), [2]=t0 (step)

__device__ __forceinline__ float fset_ge30(float a) {
    float r;
    asm("set.ge.f32.f32 %0, %1, %2;" : "=f"(r) : "f"(a), "f"(30.0f));
    return r;
}
__device__ __forceinline__ void st_rel(int* p, int v) {
    asm volatile("st.release.cta.u32 [%0], %1;" :: "l"(p), "r"(v) : "memory");
}
__device__ __forceinline__ int ld_acq(int* p) {
    int v;
    asm volatile("ld.acquire.cta.u32 %0, [%1];" : "=r"(v) : "l"(p) : "memory");
    return v;
}
__device__ __forceinline__ int fb(float x) { return __float_as_int(x); }

__global__ void __launch_bounds__(128, 1)
izh_sim(const float* __restrict__ in_mat, int n_mat,
        const float* __restrict__ w12, float* __restrict__ out, int T) {
    __shared__ __align__(16) float ring0[256 * 8];   // z2,z3,z4,v4 | v2,v3,_,_
    __shared__ __align__(16) float ring1[256 * 4];   // z5,v5,z6,v6
    __shared__ float auxst[16 * 8];                  // warp0 state @ batch starts
    __shared__ unsigned shash[NSLOT];
    __shared__ int     sbat[NSLOT];
    __shared__ float   ssnap[NSLOT][13];
    __shared__ float red[4];
    __shared__ int fl[4];   // [0] w0 batches, [1] w1 batches, [2] consumer, [3] det

    const int tid = threadIdx.x;
    if (tid == 0) { fl[0] = 0; fl[1] = 0; fl[2] = 0; fl[3] = 0; }
    if (tid < NSLOT) { shash[tid] = 0u; sbat[tid] = -1; }

    // ---- reduction: sum(input_mat) ----
    float s = 0.0f;
    for (int i = tid; i < n_mat; i += 128) s += in_mat[i];
    #pragma unroll
    for (int o = 16; o; o >>= 1) s += __shfl_xor_sync(0xffffffffu, s, o);
    if ((tid & 31) == 0) red[tid >> 5] = s;
    __syncthreads();

    const int nbat = (T + BATCH - 1) / BATCH;

    // ================= warp0 lane0: LLBN -> EBN -> IFN =================
    if (tid == 0) {
        const float total = red[0] + red[1] + red[2] + red[3];
        const float z_plus = total * w12[0];
        const float C2 = 35.0f + 0.25f * w12[2] * (z_plus * w12[1]);
        const float B2 = 0.25f * w12[3];
        const float A2 = -0.25f * w12[2] * w12[7];
        const float C3 = 35.0f + 0.25f * (z_plus * w12[4]);
        const float A3 = 0.25f * w12[5];
        const float A4 = 0.25f * w12[6];

        float v2 = -60.0f, u2 = 4.5f;
        float v3 = -64.0f, u3 = -16.0f;
        float v4 = -64.0f, u4 = -16.0f;
        float z2p = 0.0f, z4p = 0.0f;

        int si = 0;
        for (int b = 0; b < nbat; ++b) {
            if (ld_acq(&fl[3])) break;
            bool stop = false;
            while (b - ld_acq(&fl[2]) >= RING_BATCHES) {
                if (ld_acq(&fl[3])) { stop = true; break; }
            }
            if (stop) break;
            {   // publish state at this batch start (released by fl[0]=b+1)
                float* a = &auxst[(b & AUX_MASK) * 8];
                a[0] = v2; a[1] = u2; a[2] = v3; a[3] = u3;
                a[4] = v4; a[5] = u4; a[6] = z2p; a[7] = z4p;
            }
            const int n = min(BATCH, T - b * BATCH);
            #pragma unroll 4
            for (int i = 0; i < n; ++i, ++si) {
                // LLBN (a=.1,b=-.075,c=-55,d=6)
                float vv2 = v2 * v2;
                float b2  = fmaf(vv2, 0.01f, fmaf(v2, 2.25f, fmaf(u2, -0.25f, C2)));
                float v12 = fmaf(z4p, A2, fmaf(z2p, B2, b2));
                float z2  = fset_ge30(v12);
                float nu2 = fmaf(u2, 0.975f, v2 * -0.001875f);
                v2 = fmaf(z2, -55.0f - v12, v12);
                u2 = fmaf(z2, 6.0f, nu2);
                // EBN (a=.02,b=.25,c=-55,d=.05)
                float vv3 = v3 * v3;
                float b3  = fmaf(vv3, 0.01f, fmaf(v3, 2.25f, fmaf(u3, -0.25f, C3)));
                float v13 = fmaf(z2, A3, b3);
                float z3  = fset_ge30(v13);
                float nu3 = fmaf(u3, 0.995f, v3 * 0.00125f);
                v3 = fmaf(z3, -55.0f - v13, v13);
                u3 = fmaf(z3, 0.05f, nu3);
                // IFN (a=.02,b=.25,c=-65,d=6)
                float vv4 = v4 * v4;
                float b4  = fmaf(vv4, 0.01f, fmaf(v4, 2.25f, fmaf(u4, -0.25f, 35.0f)));
                float v14 = fmaf(z3, A4, b4);
                float z4  = fset_ge30(v14);
                float nu4 = fmaf(u4, 0.995f, v4 * 0.00125f);
                v4 = fmaf(z4, -65.0f - v14, v14);
                u4 = fmaf(z4, 6.0f, nu4);

                z2p = z2; z4p = z4;
                // publish: one STS.128 + one STS.64
                const int idx = (si & RS_MASK) * 8;
                *(float4*)&ring0[idx]     = make_float4(z2, z3, z4, v4);
                *(float2*)&ring0[idx + 4] = make_float2(v2, v3);
            }
            st_rel(&fl[0], b + 1);
        }
    }

    // ================= warp1 lane0: TN -> MN + every-boundary detection ========
    if (tid == 32) {
        const float A5 = 0.25f * w12[9] * w12[8];
        const float B5 = 0.25f * w12[10];
        const float A6 = 0.25f * w12[11];
        float v5 = -70.0f, u5 = -14.0f;
        float v6 = -64.0f, u6 = -16.0f;
        float z5p = 0.0f;
        bool fired = false;
        int t0b = 0, tcb = 0;

        int si = 0;
        for (int b = 0; b < nbat; ++b) {
            while (ld_acq(&fl[0]) <= b) { }
            if (b >= 1) {
                const float* a = &auxst[(b & AUX_MASK) * 8];
                unsigned h = 0x811C9DC5u;
                h = h * 0x01000193u + (unsigned)fb(a[0]);
                h = h * 0x01000193u + (unsigned)fb(a[1]);
                h = h * 0x01000193u + (unsigned)fb(a[2]);
                h = h * 0x01000193u + (unsigned)fb(a[3]);
                h = h * 0x01000193u + (unsigned)fb(a[4]);
                h = h * 0x01000193u + (unsigned)fb(a[5]);
                h = h * 0x01000193u + (unsigned)fb(a[6]);
                h = h * 0x01000193u + (unsigned)fb(a[7]);
                h = h * 0x01000193u + (unsigned)fb(v5);
                h = h * 0x01000193u + (unsigned)fb(u5);
                h = h * 0x01000193u + (unsigned)fb(v6);
                h = h * 0x01000193u + (unsigned)fb(u6);
                h = h * 0x01000193u + (unsigned)fb(z5p);
                int hit = -1;
                #pragma unroll
                for (int k = 0; k < NSLOT; ++k)
                    if (shash[k] == h && sbat[k] >= 0) hit = k;
                if (hit >= 0) {
                    bool eq = (fb(a[0]) == fb(ssnap[hit][0])) &
                              (fb(a[1]) == fb(ssnap[hit][1])) &
                              (fb(a[2]) == fb(ssnap[hit][2])) &
                              (fb(a[3]) == fb(ssnap[hit][3])) &
                              (fb(a[4]) == fb(ssnap[hit][4])) &
                              (fb(a[5]) == fb(ssnap[hit][5])) &
                              (fb(a[6]) == fb(ssnap[hit][6])) &
                              (fb(a[7]) == fb(ssnap[hit][7])) &
                              (fb(v5)   == fb(ssnap[hit][8])) &
                              (fb(u5)   == fb(ssnap[hit][9])) &
                              (fb(v6)   == fb(ssnap[hit][10])) &
                              (fb(u6)   == fb(ssnap[hit][11])) &
                              (fb(z5p)  == fb(ssnap[hit][12]));
                    if (eq && sbat[hit] < b) {
                        fired = true; t0b = sbat[hit]; tcb = b;
                        st_rel(&fl[3], 1);
                        break;
                    }
                }
                {   // arm this boundary
                    int sl = b % NSLOT;
                    shash[sl] = h; sbat[sl] = b;
                    ssnap[sl][0] = a[0]; ssnap[sl][1] = a[1];
                    ssnap[sl][2] = a[2]; ssnap[sl][3] = a[3];
                    ssnap[sl][4] = a[4]; ssnap[sl][5] = a[5];
                    ssnap[sl][6] = a[6]; ssnap[sl][7] = a[7];
                    ssnap[sl][8] = v5;  ssnap[sl][9] = u5;
                    ssnap[sl][10] = v6; ssnap[sl][11] = u6;
                    ssnap[sl][12] = z5p;
                }
            }
            const int n = min(BATCH, T - b * BATCH);
            #pragma unroll 4
            for (int i = 0; i < n; ++i, ++si) {
                float z3 = ring0[(si & RS_MASK) * 8 + 1];
                // TN (a=.02,b=.2,c=-65,d=6)
                float vv5 = v5 * v5;
                float b5  = fmaf(vv5, 0.01f, fmaf(v5, 2.25f, fmaf(u5, -0.25f, 35.0f)));
                float v15 = fmaf(z5p, B5, fmaf(z3, A5, b5));
                float z5  = fset_ge30(v15);
                float nu5 = fmaf(u5, 0.995f, v5 * 0.001f);
                v5 = fmaf(z5, -65.0f - v15, v15);
                u5 = fmaf(z5, 6.0f, nu5);
                // MN (a=.02,b=.25,c=-65,d=6)
                float vv6 = v6 * v6;
                float b6  = fmaf(vv6, 0.01f, fmaf(v6, 2.25f, fmaf(u6, -0.25f, 35.0f)));
                float v16 = fmaf(z5, A6, b6);
                float z6  = fset_ge30(v16);
                float nu6 = fmaf(u6, 0.995f, v6 * 0.00125f);
                v6 = fmaf(z6, -65.0f - v16, v16);
                u6 = fmaf(z6, 6.0f, nu6);

                z5p = z5;
                ((float4*)&ring1[(si & RS_MASK) * 4])[0] = make_float4(z5, v5, z6, v6);
            }
            st_rel(&fl[1], b + 1);
        }
        g_det[0] = fired ? 1 : 0;
        g_det[1] = tcb * BATCH;
        g_det[2] = t0b * BATCH;
    }

    // ================= warp2: store warp =================
    if (tid >= 64 && tid < 96) {
        const int lane = tid - 64;
        // rows: z2 z3 z4 z5 z6 v2 v3 v4 v5 v6
        // buf:   0  0  0  1  1  0  0  0  1  1   (mask 0x318)
        // col:   0  1  2  0  2  4  5  3  1  3
        for (int b = 0; b < nbat; ++b) {
            bool stop = false;
            for (;;) {
                if (ld_acq(&fl[1]) > b) break;
                if (ld_acq(&fl[3]) && ld_acq(&fl[1]) <= b) { stop = true; break; }
            }
            if (stop) break;
            const int base = b * BATCH;
            const int n = min(BATCH, T - base);
            if ((T & 3) == 0) {
                const int quads = n >> 2;
                const int units = 10 * quads;
                for (int u = lane; u < units; u += 32) {
                    const int row = u / quads;
                    const int q   = u - row * quads;
                    const int st  = base + q * 4;
                    const int buf = (0x318 >> row) & 1;
                    const int col = (row < 8) ? ((0x35420210u >> (4 * row)) & 15)
                                              : ((0x31u >> (4 * (row - 8))) & 15);
                    float x0, x1, x2, x3;
                    if (buf == 0) {
                        x0 = ring0[((st + 0) & RS_MASK) * 8 + col];
                        x1 = ring0[((st + 1) & RS_MASK) * 8 + col];
                        x2 = ring0[((st + 2) & RS_MASK) * 8 + col];
                        x3 = ring0[((st + 3) & RS_MASK) * 8 + col];
                    } else {
                        x0 = ring1[((st + 0) & RS_MASK) * 4 + col];
                        x1 = ring1[((st + 1) & RS_MASK) * 4 + col];
                        x2 = ring1[((st + 2) & RS_MASK) * 4 + col];
                        x3 = ring1[((st + 3) & RS_MASK) * 4 + col];
                    }
                    *(float4*)&out[row * T + st] = make_float4(x0, x1, x2, x3);
                }
            } else {
                const int units = 10 * n;
                for (int u = lane; u < units; u += 32) {
                    const int row = u / n;
                    const int i   = u - row * n;
                    const int st  = base + i;
                    const int buf = (0x318 >> row) & 1;
                    const int col = (row < 8) ? ((0x35420210u >> (4 * row)) & 15)
                                              : ((0x31u >> (4 * (row - 8))) & 15);
                    float x = buf ? ring1[(st & RS_MASK) * 4 + col]
                                  : ring0[(st & RS_MASK) * 8 + col];
                    out[row * T + st] = x;
                }
            }
            __syncwarp();
            if (lane == 0) st_rel(&fl[2], b + 1);
        }
    }
}

// Grid-parallel periodic tail fill: out[r][t] = out[r][t0 + (t-t0) mod P], t >= tcut.
__global__ void izh_tail_copy(float* __restrict__ out, int T) {
    if (!g_det[0]) return;
    const int tcut = g_det[1];
    const int t0   = g_det[2];
    const int P    = tcut - t0;
    const int tail = T - tcut;
    if (tail <= 0 || P <= 0) return;
    const int total = 10 * tail;
    for (int idx = blockIdx.x * blockDim.x + threadIdx.x; idx < total;
         idx += gridDim.x * blockDim.x) {
        const int row = idx / tail;
        const int t   = tcut + (idx - row * tail);
        const int src = t0 + (t - t0) % P;
        out[row * T + t] = out[row * T + src];
    }
}

extern "C" void kernel_launch(void* const* d_in, const int* in_sizes, int n_in,
                              void* d_out, int out_size) {
    const float* in_mat = (const float*)d_in[0];
    const float* w12    = (const float*)d_in[1];
    int n_mat = in_sizes[0];
    int T = out_size / 10;
    izh_sim<<<1, 128>>>(in_mat, n_mat, w12, (float*)d_out, T);
    izh_tail_copy<<<256, 256>>>((float*)d_out, T);
}

// round 16
// speedup vs baseline: 1.3353x; 1.0567x over previous
#include <cuda_runtime.h>

// Izhikevich 6-neuron network, T sequential steps. R15 (bit-exact orbit A,
// every-boundary exact cycle detection, STS.128+STS.64 publish, grid tail copy)
// + FULL 16-step unroll of both sim warps' inner loops (cross-step ILP).
// warp0: LLBN->EBN->IFN. warp1: TN->MN + detection. warp2: store.
// Output: [spikes[5][T] | volts[5][T]]

#define BATCH 16
#define RS_MASK 255
#define RING_BATCHES 4
#define AUX_MASK 15
#define NSLOT 28

__device__ int g_det[3];     // [0]=flag, [1]=tcut (step), [2]=t0 (step)

__device__ __forceinline__ float fset_ge30(float a) {
    float r;
    asm("set.ge.f32.f32 %0, %1, %2;" : "=f"(r) : "f"(a), "f"(30.0f));
    return r;
}
__device__ __forceinline__ void st_rel(int* p, int v) {
    asm volatile("st.release.cta.u32 [%0], %1;" :: "l"(p), "r"(v) : "memory");
}
__device__ __forceinline__ int ld_acq(int* p) {
    int v;
    asm volatile("ld.acquire.cta.u32 %0, [%1];" : "=r"(v) : "l"(p) : "memory");
    return v;
}
__device__ __forceinline__ int fb(float x) { return __float_as_int(x); }

__global__ void __launch_bounds__(128, 1)
izh_sim(const float* __restrict__ in_mat, int n_mat,
        const float* __restrict__ w12, float* __restrict__ out, int T) {
    __shared__ __align__(16) float ring0[256 * 8];   // z2,z3,z4,v4 | v2,v3,_,_
    __shared__ __align__(16) float ring1[256 * 4];   // z5,v5,z6,v6
    __shared__ float auxst[16 * 8];                  // warp0 state @ batch starts
    __shared__ unsigned shash[NSLOT];
    __shared__ int     sbat[NSLOT];
    __shared__ float   ssnap[NSLOT][13];
    __shared__ float red[4];
    __shared__ int fl[4];   // [0] w0 batches, [1] w1 batches, [2] consumer, [3] det

    const int tid = threadIdx.x;
    if (tid == 0) { fl[0] = 0; fl[1] = 0; fl[2] = 0; fl[3] = 0; }
    if (tid < NSLOT) { shash[tid] = 0u; sbat[tid] = -1; }

    // ---- reduction: sum(input_mat) ----
    float s = 0.0f;
    for (int i = tid; i < n_mat; i += 128) s += in_mat[i];
    #pragma unroll
    for (int o = 16; o; o >>= 1) s += __shfl_xor_sync(0xffffffffu, s, o);
    if ((tid & 31) == 0) red[tid >> 5] = s;
    __syncthreads();

    const int nbat = (T + BATCH - 1) / BATCH;

    // ================= warp0 lane0: LLBN -> EBN -> IFN =================
    if (tid == 0) {
        const float total = red[0] + red[1] + red[2] + red[3];
        const float z_plus = total * w12[0];
        const float C2 = 35.0f + 0.25f * w12[2] * (z_plus * w12[1]);
        const float B2 = 0.25f * w12[3];
        const float A2 = -0.25f * w12[2] * w12[7];
        const float C3 = 35.0f + 0.25f * (z_plus * w12[4]);
        const float A3 = 0.25f * w12[5];
        const float A4 = 0.25f * w12[6];

        float v2 = -60.0f, u2 = 4.5f;
        float v3 = -64.0f, u3 = -16.0f;
        float v4 = -64.0f, u4 = -16.0f;
        float z2p = 0.0f, z4p = 0.0f;

        int si = 0;
        for (int b = 0; b < nbat; ++b) {
            if (ld_acq(&fl[3])) break;
            bool stop = false;
            while (b - ld_acq(&fl[2]) >= RING_BATCHES) {
                if (ld_acq(&fl[3])) { stop = true; break; }
            }
            if (stop) break;
            {   // publish state at this batch start (released by fl[0]=b+1)
                float* a = &auxst[(b & AUX_MASK) * 8];
                a[0] = v2; a[1] = u2; a[2] = v3; a[3] = u3;
                a[4] = v4; a[5] = u4; a[6] = z2p; a[7] = z4p;
            }
            const int n = min(BATCH, T - b * BATCH);
            if (n == BATCH) {
                #pragma unroll
                for (int i = 0; i < BATCH; ++i, ++si) {
                    // LLBN (a=.1,b=-.075,c=-55,d=6)
                    float vv2 = v2 * v2;
                    float b2  = fmaf(vv2, 0.01f, fmaf(v2, 2.25f, fmaf(u2, -0.25f, C2)));
                    float v12 = fmaf(z4p, A2, fmaf(z2p, B2, b2));
                    float z2  = fset_ge30(v12);
                    float nu2 = fmaf(u2, 0.975f, v2 * -0.001875f);
                    v2 = fmaf(z2, -55.0f - v12, v12);
                    u2 = fmaf(z2, 6.0f, nu2);
                    // EBN (a=.02,b=.25,c=-55,d=.05)
                    float vv3 = v3 * v3;
                    float b3  = fmaf(vv3, 0.01f, fmaf(v3, 2.25f, fmaf(u3, -0.25f, C3)));
                    float v13 = fmaf(z2, A3, b3);
                    float z3  = fset_ge30(v13);
                    float nu3 = fmaf(u3, 0.995f, v3 * 0.00125f);
                    v3 = fmaf(z3, -55.0f - v13, v13);
                    u3 = fmaf(z3, 0.05f, nu3);
                    // IFN (a=.02,b=.25,c=-65,d=6)
                    float vv4 = v4 * v4;
                    float b4  = fmaf(vv4, 0.01f, fmaf(v4, 2.25f, fmaf(u4, -0.25f, 35.0f)));
                    float v14 = fmaf(z3, A4, b4);
                    float z4  = fset_ge30(v14);
                    float nu4 = fmaf(u4, 0.995f, v4 * 0.00125f);
                    v4 = fmaf(z4, -65.0f - v14, v14);
                    u4 = fmaf(z4, 6.0f, nu4);

                    z2p = z2; z4p = z4;
                    const int idx = (si & RS_MASK) * 8;
                    *(float4*)&ring0[idx]     = make_float4(z2, z3, z4, v4);
                    *(float2*)&ring0[idx + 4] = make_float2(v2, v3);
                }
            } else {
                for (int i = 0; i < n; ++i, ++si) {
                    float vv2 = v2 * v2;
                    float b2  = fmaf(vv2, 0.01f, fmaf(v2, 2.25f, fmaf(u2, -0.25f, C2)));
                    float v12 = fmaf(z4p, A2, fmaf(z2p, B2, b2));
                    float z2  = fset_ge30(v12);
                    float nu2 = fmaf(u2, 0.975f, v2 * -0.001875f);
                    v2 = fmaf(z2, -55.0f - v12, v12);
                    u2 = fmaf(z2, 6.0f, nu2);
                    float vv3 = v3 * v3;
                    float b3  = fmaf(vv3, 0.01f, fmaf(v3, 2.25f, fmaf(u3, -0.25f, C3)));
                    float v13 = fmaf(z2, A3, b3);
                    float z3  = fset_ge30(v13);
                    float nu3 = fmaf(u3, 0.995f, v3 * 0.00125f);
                    v3 = fmaf(z3, -55.0f - v13, v13);
                    u3 = fmaf(z3, 0.05f, nu3);
                    float vv4 = v4 * v4;
                    float b4  = fmaf(vv4, 0.01f, fmaf(v4, 2.25f, fmaf(u4, -0.25f, 35.0f)));
                    float v14 = fmaf(z3, A4, b4);
                    float z4  = fset_ge30(v14);
                    float nu4 = fmaf(u4, 0.995f, v4 * 0.00125f);
                    v4 = fmaf(z4, -65.0f - v14, v14);
                    u4 = fmaf(z4, 6.0f, nu4);
                    z2p = z2; z4p = z4;
                    const int idx = (si & RS_MASK) * 8;
                    *(float4*)&ring0[idx]     = make_float4(z2, z3, z4, v4);
                    *(float2*)&ring0[idx + 4] = make_float2(v2, v3);
                }
            }
            st_rel(&fl[0], b + 1);
        }
    }

    // ================= warp1 lane0: TN -> MN + every-boundary detection ========
    if (tid == 32) {
        const float A5 = 0.25f * w12[9] * w12[8];
        const float B5 = 0.25f * w12[10];
        const float A6 = 0.25f * w12[11];
        float v5 = -70.0f, u5 = -14.0f;
        float v6 = -64.0f, u6 = -16.0f;
        float z5p = 0.0f;
        bool fired = false;
        int t0b = 0, tcb = 0;

        int si = 0;
        for (int b = 0; b < nbat; ++b) {
            while (ld_acq(&fl[0]) <= b) { }
            if (b >= 1) {
                const float* a = &auxst[(b & AUX_MASK) * 8];
                unsigned h = 0x811C9DC5u;
                h = h * 0x01000193u + (unsigned)fb(a[0]);
                h = h * 0x01000193u + (unsigned)fb(a[1]);
                h = h * 0x01000193u + (unsigned)fb(a[2]);
                h = h * 0x01000193u + (unsigned)fb(a[3]);
                h = h * 0x01000193u + (unsigned)fb(a[4]);
                h = h * 0x01000193u + (unsigned)fb(a[5]);
                h = h * 0x01000193u + (unsigned)fb(a[6]);
                h = h * 0x01000193u + (unsigned)fb(a[7]);
                h = h * 0x01000193u + (unsigned)fb(v5);
                h = h * 0x01000193u + (unsigned)fb(u5);
                h = h * 0x01000193u + (unsigned)fb(v6);
                h = h * 0x01000193u + (unsigned)fb(u6);
                h = h * 0x01000193u + (unsigned)fb(z5p);
                int hit = -1;
                #pragma unroll
                for (int k = 0; k < NSLOT; ++k)
                    if (shash[k] == h && sbat[k] >= 0) hit = k;
                if (hit >= 0) {
                    bool eq = (fb(a[0]) == fb(ssnap[hit][0])) &
                              (fb(a[1]) == fb(ssnap[hit][1])) &
                              (fb(a[2]) == fb(ssnap[hit][2])) &
                              (fb(a[3]) == fb(ssnap[hit][3])) &
                              (fb(a[4]) == fb(ssnap[hit][4])) &
                              (fb(a[5]) == fb(ssnap[hit][5])) &
                              (fb(a[6]) == fb(ssnap[hit][6])) &
                              (fb(a[7]) == fb(ssnap[hit][7])) &
                              (fb(v5)   == fb(ssnap[hit][8])) &
                              (fb(u5)   == fb(ssnap[hit][9])) &
                              (fb(v6)   == fb(ssnap[hit][10])) &
                              (fb(u6)   == fb(ssnap[hit][11])) &
                              (fb(z5p)  == fb(ssnap[hit][12]));
                    if (eq && sbat[hit] < b) {
                        fired = true; t0b = sbat[hit]; tcb = b;
                        st_rel(&fl[3], 1);
                        break;
                    }
                }
                {   // arm this boundary
                    int sl = b % NSLOT;
                    shash[sl] = h; sbat[sl] = b;
                    ssnap[sl][0] = a[0]; ssnap[sl][1] = a[1];
                    ssnap[sl][2] = a[2]; ssnap[sl][3] = a[3];
                    ssnap[sl][4] = a[4]; ssnap[sl][5] = a[5];
                    ssnap[sl][6] = a[6]; ssnap[sl][7] = a[7];
                    ssnap[sl][8] = v5;  ssnap[sl][9] = u5;
                    ssnap[sl][10] = v6; ssnap[sl][11] = u6;
                    ssnap[sl][12] = z5p;
                }
            }
            const int n = min(BATCH, T - b * BATCH);
            if (n == BATCH) {
                #pragma unroll
                for (int i = 0; i < BATCH; ++i, ++si) {
                    float z3 = ring0[(si & RS_MASK) * 8 + 1];
                    // TN (a=.02,b=.2,c=-65,d=6)
                    float vv5 = v5 * v5;
                    float b5  = fmaf(vv5, 0.01f, fmaf(v5, 2.25f, fmaf(u5, -0.25f, 35.0f)));
                    float v15 = fmaf(z5p, B5, fmaf(z3, A5, b5));
                    float z5  = fset_ge30(v15);
                    float nu5 = fmaf(u5, 0.995f, v5 * 0.001f);
                    v5 = fmaf(z5, -65.0f - v15, v15);
                    u5 = fmaf(z5, 6.0f, nu5);
                    // MN (a=.02,b=.25,c=-65,d=6)
                    float vv6 = v6 * v6;
                    float b6  = fmaf(vv6, 0.01f, fmaf(v6, 2.25f, fmaf(u6, -0.25f, 35.0f)));
                    float v16 = fmaf(z5, A6, b6);
                    float z6  = fset_ge30(v16);
                    float nu6 = fmaf(u6, 0.995f, v6 * 0.00125f);
                    v6 = fmaf(z6, -65.0f - v16, v16);
                    u6 = fmaf(z6, 6.0f, nu6);

                    z5p = z5;
                    ((float4*)&ring1[(si & RS_MASK) * 4])[0] = make_float4(z5, v5, z6, v6);
                }
            } else {
                for (int i = 0; i < n; ++i, ++si) {
                    float z3 = ring0[(si & RS_MASK) * 8 + 1];
                    float vv5 = v5 * v5;
                    float b5  = fmaf(vv5, 0.01f, fmaf(v5, 2.25f, fmaf(u5, -0.25f, 35.0f)));
                    float v15 = fmaf(z5p, B5, fmaf(z3, A5, b5));
                    float z5  = fset_ge30(v15);
                    float nu5 = fmaf(u5, 0.995f, v5 * 0.001f);
                    v5 = fmaf(z5, -65.0f - v15, v15);
                    u5 = fmaf(z5, 6.0f, nu5);
                    float vv6 = v6 * v6;
                    float b6  = fmaf(vv6, 0.01f, fmaf(v6, 2.25f, fmaf(u6, -0.25f, 35.0f)));
                    float v16 = fmaf(z5, A6, b6);
                    float z6  = fset_ge30(v16);
                    float nu6 = fmaf(u6, 0.995f, v6 * 0.00125f);
                    v6 = fmaf(z6, -65.0f - v16, v16);
                    u6 = fmaf(z6, 6.0f, nu6);
                    z5p = z5;
                    ((float4*)&ring1[(si & RS_MASK) * 4])[0] = make_float4(z5, v5, z6, v6);
                }
            }
            st_rel(&fl[1], b + 1);
        }
        g_det[0] = fired ? 1 : 0;
        g_det[1] = tcb * BATCH;
        g_det[2] = t0b * BATCH;
    }

    // ================= warp2: store warp =================
    if (tid >= 64 && tid < 96) {
        const int lane = tid - 64;
        // rows: z2 z3 z4 z5 z6 v2 v3 v4 v5 v6
        // buf:   0  0  0  1  1  0  0  0  1  1   (mask 0x318)
        // col:   0  1  2  0  2  4  5  3  1  3
        for (int b = 0; b < nbat; ++b) {
            bool stop = false;
            for (;;) {
                if (ld_acq(&fl[1]) > b) break;
                if (ld_acq(&fl[3]) && ld_acq(&fl[1]) <= b) { stop = true; break; }
            }
            if (stop) break;
            const int base = b * BATCH;
            const int n = min(BATCH, T - base);
            if ((T & 3) == 0) {
                const int quads = n >> 2;
                const int units = 10 * quads;
                for (int u = lane; u < units; u += 32) {
                    const int row = u / quads;
                    const int q   = u - row * quads;
                    const int st  = base + q * 4;
                    const int buf = (0x318 >> row) & 1;
                    const int col = (row < 8) ? ((0x35420210u >> (4 * row)) & 15)
                                              : ((0x31u >> (4 * (row - 8))) & 15);
                    float x0, x1, x2, x3;
                    if (buf == 0) {
                        x0 = ring0[((st + 0) & RS_MASK) * 8 + col];
                        x1 = ring0[((st + 1) & RS_MASK) * 8 + col];
                        x2 = ring0[((st + 2) & RS_MASK) * 8 + col];
                        x3 = ring0[((st + 3) & RS_MASK) * 8 + col];
                    } else {
                        x0 = ring1[((st + 0) & RS_MASK) * 4 + col];
                        x1 = ring1[((st + 1) & RS_MASK) * 4 + col];
                        x2 = ring1[((st + 2) & RS_MASK) * 4 + col];
                        x3 = ring1[((st + 3) & RS_MASK) * 4 + col];
                    }
                    *(float4*)&out[row * T + st] = make_float4(x0, x1, x2, x3);
                }
            } else {
                const int units = 10 * n;
                for (int u = lane; u < units; u += 32) {
                    const int row = u / n;
                    const int i   = u - row * n;
                    const int st  = base + i;
                    const int buf = (0x318 >> row) & 1;
                    const int col = (row < 8) ? ((0x35420210u >> (4 * row)) & 15)
                                              : ((0x31u >> (4 * (row - 8))) & 15);
                    float x = buf ? ring1[(st & RS_MASK) * 4 + col]
                                  : ring0[(st & RS_MASK) * 8 + col];
                    out[row * T + st] = x;
                }
            }
            __syncwarp();
            if (lane == 0) st_rel(&fl[2], b + 1);
        }
    }
}

// Grid-parallel periodic tail fill: out[r][t] = out[r][t0 + (t-t0) mod P], t >= tcut.
__global__ void izh_tail_copy(float* __restrict__ out, int T) {
    if (!g_det[0]) return;
    const int tcut = g_det[1];
    const int t0   = g_det[2];
    const int P    = tcut - t0;
    const int tail = T - tcut;
    if (tail <= 0 || P <= 0) return;
    const int total = 10 * tail;
    for (int idx = blockIdx.x * blockDim.x + threadIdx.x; idx < total;
         idx += gridDim.x * blockDim.x) {
        const int row = idx / tail;
        const int t   = tcut + (idx - row * tail);
        const int src = t0 + (t - t0) % P;
        out[row * T + t] = out[row * T + src];
    }
}

extern "C" void kernel_launch(void* const* d_in, const int* in_sizes, int n_in,
                              void* d_out, int out_size) {
    const float* in_mat = (const float*)d_in[0];
    const float* w12    = (const float*)d_in[1];
    int n_mat = in_sizes[0];
    int T = out_size / 10;
    izh_sim<<<1, 128>>>(in_mat, n_mat, w12, (float*)d_out, T);
    izh_tail_copy<<<256, 256>>>((float*)d_out, T);
}

// round 17
// speedup vs baseline: 1.4456x; 1.0826x over previous
#include <cuda_runtime.h>

// Izhikevich 6-neuron network, T sequential steps. R16 (bit-exact orbit A,
// every-boundary exact cycle detection, grid tail copy, full unroll)
// with BATCH widened to 32 (longer software-pipeline window, halved per-batch
// overhead; detection at 32-step boundaries — lag is a multiple of 32).
// warp0: LLBN->EBN->IFN. warp1: TN->MN + detection. warp2: store.
// Output: [spikes[5][T] | volts[5][T]]

#define BATCH 32
#define RS_MASK 255
#define RING_BATCHES 4
#define AUX_MASK 15
#define NSLOT 28

__device__ int g_det[3];     // [0]=flag, [1]=tcut (step), [2]=t0 (step)

__device__ __forceinline__ float fset_ge30(float a) {
    float r;
    asm("set.ge.f32.f32 %0, %1, %2;" : "=f"(r) : "f"(a), "f"(30.0f));
    return r;
}
__device__ __forceinline__ void st_rel(int* p, int v) {
    asm volatile("st.release.cta.u32 [%0], %1;" :: "l"(p), "r"(v) : "memory");
}
__device__ __forceinline__ int ld_acq(int* p) {
    int v;
    asm volatile("ld.acquire.cta.u32 %0, [%1];" : "=r"(v) : "l"(p) : "memory");
    return v;
}
__device__ __forceinline__ int fb(float x) { return __float_as_int(x); }

__global__ void __launch_bounds__(128, 1)
izh_sim(const float* __restrict__ in_mat, int n_mat,
        const float* __restrict__ w12, float* __restrict__ out, int T) {
    __shared__ __align__(16) float ring0[256 * 8];   // z2,z3,z4,v4 | v2,v3,_,_
    __shared__ __align__(16) float ring1[256 * 4];   // z5,v5,z6,v6
    __shared__ float auxst[16 * 8];                  // warp0 state @ batch starts
    __shared__ unsigned shash[NSLOT];
    __shared__ int     sbat[NSLOT];
    __shared__ float   ssnap[NSLOT][13];
    __shared__ float red[4];
    __shared__ int fl[4];   // [0] w0 batches, [1] w1 batches, [2] consumer, [3] det

    const int tid = threadIdx.x;
    if (tid == 0) { fl[0] = 0; fl[1] = 0; fl[2] = 0; fl[3] = 0; }
    if (tid < NSLOT) { shash[tid] = 0u; sbat[tid] = -1; }

    // ---- reduction: sum(input_mat) ----
    float s = 0.0f;
    for (int i = tid; i < n_mat; i += 128) s += in_mat[i];
    #pragma unroll
    for (int o = 16; o; o >>= 1) s += __shfl_xor_sync(0xffffffffu, s, o);
    if ((tid & 31) == 0) red[tid >> 5] = s;
    __syncthreads();

    const int nbat = (T + BATCH - 1) / BATCH;

    // ================= warp0 lane0: LLBN -> EBN -> IFN =================
    if (tid == 0) {
        const float total = red[0] + red[1] + red[2] + red[3];
        const float z_plus = total * w12[0];
        const float C2 = 35.0f + 0.25f * w12[2] * (z_plus * w12[1]);
        const float B2 = 0.25f * w12[3];
        const float A2 = -0.25f * w12[2] * w12[7];
        const float C3 = 35.0f + 0.25f * (z_plus * w12[4]);
        const float A3 = 0.25f * w12[5];
        const float A4 = 0.25f * w12[6];

        float v2 = -60.0f, u2 = 4.5f;
        float v3 = -64.0f, u3 = -16.0f;
        float v4 = -64.0f, u4 = -16.0f;
        float z2p = 0.0f, z4p = 0.0f;

        int si = 0;
        for (int b = 0; b < nbat; ++b) {
            if (ld_acq(&fl[3])) break;
            bool stop = false;
            while (b - ld_acq(&fl[2]) >= RING_BATCHES) {
                if (ld_acq(&fl[3])) { stop = true; break; }
            }
            if (stop) break;
            {   // publish state at this batch start (released by fl[0]=b+1)
                float* a = &auxst[(b & AUX_MASK) * 8];
                a[0] = v2; a[1] = u2; a[2] = v3; a[3] = u3;
                a[4] = v4; a[5] = u4; a[6] = z2p; a[7] = z4p;
            }
            const int n = min(BATCH, T - b * BATCH);
            if (n == BATCH) {
                #pragma unroll
                for (int i = 0; i < BATCH; ++i, ++si) {
                    // LLBN (a=.1,b=-.075,c=-55,d=6)
                    float vv2 = v2 * v2;
                    float b2  = fmaf(vv2, 0.01f, fmaf(v2, 2.25f, fmaf(u2, -0.25f, C2)));
                    float v12 = fmaf(z4p, A2, fmaf(z2p, B2, b2));
                    float z2  = fset_ge30(v12);
                    float nu2 = fmaf(u2, 0.975f, v2 * -0.001875f);
                    v2 = fmaf(z2, -55.0f - v12, v12);
                    u2 = fmaf(z2, 6.0f, nu2);
                    // EBN (a=.02,b=.25,c=-55,d=.05)
                    float vv3 = v3 * v3;
                    float b3  = fmaf(vv3, 0.01f, fmaf(v3, 2.25f, fmaf(u3, -0.25f, C3)));
                    float v13 = fmaf(z2, A3, b3);
                    float z3  = fset_ge30(v13);
                    float nu3 = fmaf(u3, 0.995f, v3 * 0.00125f);
                    v3 = fmaf(z3, -55.0f - v13, v13);
                    u3 = fmaf(z3, 0.05f, nu3);
                    // IFN (a=.02,b=.25,c=-65,d=6)
                    float vv4 = v4 * v4;
                    float b4  = fmaf(vv4, 0.01f, fmaf(v4, 2.25f, fmaf(u4, -0.25f, 35.0f)));
                    float v14 = fmaf(z3, A4, b4);
                    float z4  = fset_ge30(v14);
                    float nu4 = fmaf(u4, 0.995f, v4 * 0.00125f);
                    v4 = fmaf(z4, -65.0f - v14, v14);
                    u4 = fmaf(z4, 6.0f, nu4);

                    z2p = z2; z4p = z4;
                    const int idx = (si & RS_MASK) * 8;
                    *(float4*)&ring0[idx]     = make_float4(z2, z3, z4, v4);
                    *(float2*)&ring0[idx + 4] = make_float2(v2, v3);
                }
            } else {
                for (int i = 0; i < n; ++i, ++si) {
                    float vv2 = v2 * v2;
                    float b2  = fmaf(vv2, 0.01f, fmaf(v2, 2.25f, fmaf(u2, -0.25f, C2)));
                    float v12 = fmaf(z4p, A2, fmaf(z2p, B2, b2));
                    float z2  = fset_ge30(v12);
                    float nu2 = fmaf(u2, 0.975f, v2 * -0.001875f);
                    v2 = fmaf(z2, -55.0f - v12, v12);
                    u2 = fmaf(z2, 6.0f, nu2);
                    float vv3 = v3 * v3;
                    float b3  = fmaf(vv3, 0.01f, fmaf(v3, 2.25f, fmaf(u3, -0.25f, C3)));
                    float v13 = fmaf(z2, A3, b3);
                    float z3  = fset_ge30(v13);
                    float nu3 = fmaf(u3, 0.995f, v3 * 0.00125f);
                    v3 = fmaf(z3, -55.0f - v13, v13);
                    u3 = fmaf(z3, 0.05f, nu3);
                    float vv4 = v4 * v4;
                    float b4  = fmaf(vv4, 0.01f, fmaf(v4, 2.25f, fmaf(u4, -0.25f, 35.0f)));
                    float v14 = fmaf(z3, A4, b4);
                    float z4  = fset_ge30(v14);
                    float nu4 = fmaf(u4, 0.995f, v4 * 0.00125f);
                    v4 = fmaf(z4, -65.0f - v14, v14);
                    u4 = fmaf(z4, 6.0f, nu4);
                    z2p = z2; z4p = z4;
                    const int idx = (si & RS_MASK) * 8;
                    *(float4*)&ring0[idx]     = make_float4(z2, z3, z4, v4);
                    *(float2*)&ring0[idx + 4] = make_float2(v2, v3);
                }
            }
            st_rel(&fl[0], b + 1);
        }
    }

    // ================= warp1 lane0: TN -> MN + every-boundary detection ========
    if (tid == 32) {
        const float A5 = 0.25f * w12[9] * w12[8];
        const float B5 = 0.25f * w12[10];
        const float A6 = 0.25f * w12[11];
        float v5 = -70.0f, u5 = -14.0f;
        float v6 = -64.0f, u6 = -16.0f;
        float z5p = 0.0f;
        bool fired = false;
        int t0b = 0, tcb = 0;

        int si = 0;
        for (int b = 0; b < nbat; ++b) {
            while (ld_acq(&fl[0]) <= b) { }
            if (b >= 1) {
                const float* a = &auxst[(b & AUX_MASK) * 8];
                unsigned h = 0x811C9DC5u;
                h = h * 0x01000193u + (unsigned)fb(a[0]);
                h = h * 0x01000193u + (unsigned)fb(a[1]);
                h = h * 0x01000193u + (unsigned)fb(a[2]);
                h = h * 0x01000193u + (unsigned)fb(a[3]);
                h = h * 0x01000193u + (unsigned)fb(a[4]);
                h = h * 0x01000193u + (unsigned)fb(a[5]);
                h = h * 0x01000193u + (unsigned)fb(a[6]);
                h = h * 0x01000193u + (unsigned)fb(a[7]);
                h = h * 0x01000193u + (unsigned)fb(v5);
                h = h * 0x01000193u + (unsigned)fb(u5);
                h = h * 0x01000193u + (unsigned)fb(v6);
                h = h * 0x01000193u + (unsigned)fb(u6);
                h = h * 0x01000193u + (unsigned)fb(z5p);
                int hit = -1;
                #pragma unroll
                for (int k = 0; k < NSLOT; ++k)
                    if (shash[k] == h && sbat[k] >= 0) hit = k;
                if (hit >= 0) {
                    bool eq = (fb(a[0]) == fb(ssnap[hit][0])) &
                              (fb(a[1]) == fb(ssnap[hit][1])) &
                              (fb(a[2]) == fb(ssnap[hit][2])) &
                              (fb(a[3]) == fb(ssnap[hit][3])) &
                              (fb(a[4]) == fb(ssnap[hit][4])) &
                              (fb(a[5]) == fb(ssnap[hit][5])) &
                              (fb(a[6]) == fb(ssnap[hit][6])) &
                              (fb(a[7]) == fb(ssnap[hit][7])) &
                              (fb(v5)   == fb(ssnap[hit][8])) &
                              (fb(u5)   == fb(ssnap[hit][9])) &
                              (fb(v6)   == fb(ssnap[hit][10])) &
                              (fb(u6)   == fb(ssnap[hit][11])) &
                              (fb(z5p)  == fb(ssnap[hit][12]));
                    if (eq && sbat[hit] < b) {
                        fired = true; t0b = sbat[hit]; tcb = b;
                        st_rel(&fl[3], 1);
                        break;
                    }
                }
                {   // arm this boundary
                    int sl = b % NSLOT;
                    shash[sl] = h; sbat[sl] = b;
                    ssnap[sl][0] = a[0]; ssnap[sl][1] = a[1];
                    ssnap[sl][2] = a[2]; ssnap[sl][3] = a[3];
                    ssnap[sl][4] = a[4]; ssnap[sl][5] = a[5];
                    ssnap[sl][6] = a[6]; ssnap[sl][7] = a[7];
                    ssnap[sl][8] = v5;  ssnap[sl][9] = u5;
                    ssnap[sl][10] = v6; ssnap[sl][11] = u6;
                    ssnap[sl][12] = z5p;
                }
            }
            const int n = min(BATCH, T - b * BATCH);
            if (n == BATCH) {
                #pragma unroll
                for (int i = 0; i < BATCH; ++i, ++si) {
                    float z3 = ring0[(si & RS_MASK) * 8 + 1];
                    // TN (a=.02,b=.2,c=-65,d=6)
                    float vv5 = v5 * v5;
                    float b5  = fmaf(vv5, 0.01f, fmaf(v5, 2.25f, fmaf(u5, -0.25f, 35.0f)));
                    float v15 = fmaf(z5p, B5, fmaf(z3, A5, b5));
                    float z5  = fset_ge30(v15);
                    float nu5 = fmaf(u5, 0.995f, v5 * 0.001f);
                    v5 = fmaf(z5, -65.0f - v15, v15);
                    u5 = fmaf(z5, 6.0f, nu5);
                    // MN (a=.02,b=.25,c=-65,d=6)
                    float vv6 = v6 * v6;
                    float b6  = fmaf(vv6, 0.01f, fmaf(v6, 2.25f, fmaf(u6, -0.25f, 35.0f)));
                    float v16 = fmaf(z5, A6, b6);
                    float z6  = fset_ge30(v16);
                    float nu6 = fmaf(u6, 0.995f, v6 * 0.00125f);
                    v6 = fmaf(z6, -65.0f - v16, v16);
                    u6 = fmaf(z6, 6.0f, nu6);

                    z5p = z5;
                    ((float4*)&ring1[(si & RS_MASK) * 4])[0] = make_float4(z5, v5, z6, v6);
                }
            } else {
                for (int i = 0; i < n; ++i, ++si) {
                    float z3 = ring0[(si & RS_MASK) * 8 + 1];
                    float vv5 = v5 * v5;
                    float b5  = fmaf(vv5, 0.01f, fmaf(v5, 2.25f, fmaf(u5, -0.25f, 35.0f)));
                    float v15 = fmaf(z5p, B5, fmaf(z3, A5, b5));
                    float z5  = fset_ge30(v15);
                    float nu5 = fmaf(u5, 0.995f, v5 * 0.001f);
                    v5 = fmaf(z5, -65.0f - v15, v15);
                    u5 = fmaf(z5, 6.0f, nu5);
                    float vv6 = v6 * v6;
                    float b6  = fmaf(vv6, 0.01f, fmaf(v6, 2.25f, fmaf(u6, -0.25f, 35.0f)));
                    float v16 = fmaf(z5, A6, b6);
                    float z6  = fset_ge30(v16);
                    float nu6 = fmaf(u6, 0.995f, v6 * 0.00125f);
                    v6 = fmaf(z6, -65.0f - v16, v16);
                    u6 = fmaf(z6, 6.0f, nu6);
                    z5p = z5;
                    ((float4*)&ring1[(si & RS_MASK) * 4])[0] = make_float4(z5, v5, z6, v6);
                }
            }
            st_rel(&fl[1], b + 1);
        }
        g_det[0] = fired ? 1 : 0;
        g_det[1] = tcb * BATCH;
        g_det[2] = t0b * BATCH;
    }

    // ================= warp2: store warp =================
    if (tid >= 64 && tid < 96) {
        const int lane = tid - 64;
        // rows: z2 z3 z4 z5 z6 v2 v3 v4 v5 v6
        // buf:   0  0  0  1  1  0  0  0  1  1   (mask 0x318)
        // col:   0  1  2  0  2  4  5  3  1  3
        for (int b = 0; b < nbat; ++b) {
            bool stop = false;
            for (;;) {
                if (ld_acq(&fl[1]) > b) break;
                if (ld_acq(&fl[3]) && ld_acq(&fl[1]) <= b) { stop = true; break; }
            }
            if (stop) break;
            const int base = b * BATCH;
            const int n = min(BATCH, T - base);
            if ((T & 3) == 0) {
                const int quads = n >> 2;
                const int units = 10 * quads;
                for (int u = lane; u < units; u += 32) {
                    const int row = u / quads;
                    const int q   = u - row * quads;
                    const int st  = base + q * 4;
                    const int buf = (0x318 >> row) & 1;
                    const int col = (row < 8) ? ((0x35420210u >> (4 * row)) & 15)
                                              : ((0x31u >> (4 * (row - 8))) & 15);
                    float x0, x1, x2, x3;
                    if (buf == 0) {
                        x0 = ring0[((st + 0) & RS_MASK) * 8 + col];
                        x1 = ring0[((st + 1) & RS_MASK) * 8 + col];
                        x2 = ring0[((st + 2) & RS_MASK) * 8 + col];
                        x3 = ring0[((st + 3) & RS_MASK) * 8 + col];
                    } else {
                        x0 = ring1[((st + 0) & RS_MASK) * 4 + col];
                        x1 = ring1[((st + 1) & RS_MASK) * 4 + col];
                        x2 = ring1[((st + 2) & RS_MASK) * 4 + col];
                        x3 = ring1[((st + 3) & RS_MASK) * 4 + col];
                    }
                    *(float4*)&out[row * T + st] = make_float4(x0, x1, x2, x3);
                }
            } else {
                const int units = 10 * n;
                for (int u = lane; u < units; u += 32) {
                    const int row = u / n;
                    const int i   = u - row * n;
                    const int st  = base + i;
                    const int buf = (0x318 >> row) & 1;
                    const int col = (row < 8) ? ((0x35420210u >> (4 * row)) & 15)
                                              : ((0x31u >> (4 * (row - 8))) & 15);
                    float x = buf ? ring1[(st & RS_MASK) * 4 + col]
                                  : ring0[(st & RS_MASK) * 8 + col];
                    out[row * T + st] = x;
                }
            }
            __syncwarp();
            if (lane == 0) st_rel(&fl[2], b + 1);
        }
    }
}

// Grid-parallel periodic tail fill: out[r][t] = out[r][t0 + (t-t0) mod P], t >= tcut.
__global__ void izh_tail_copy(float* __restrict__ out, int T) {
    if (!g_det[0]) return;
    const int tcut = g_det[1];
    const int t0   = g_det[2];
    const int P    = tcut - t0;
    const int tail = T - tcut;
    if (tail <= 0 || P <= 0) return;
    const int total = 10 * tail;
    for (int idx = blockIdx.x * blockDim.x + threadIdx.x; idx < total;
         idx += gridDim.x * blockDim.x) {
        const int row = idx / tail;
        const int t   = tcut + (idx - row * tail);
        const int src = t0 + (t - t0) % P;
        out[row * T + t] = out[row * T + src];
    }
}

extern "C" void kernel_launch(void* const* d_in, const int* in_sizes, int n_in,
                              void* d_out, int out_size) {
    const float* in_mat = (const float*)d_in[0];
    const float* w12    = (const float*)d_in[1];
    int n_mat = in_sizes[0];
    int T = out_size / 10;
    izh_sim<<<1, 128>>>(in_mat, n_mat, w12, (float*)d_out, T);
    izh_tail_copy<<<256, 256>>>((float*)d_out, T);
}